// round 10
// baseline (speedup 1.0000x reference)
#include <cuda_runtime.h>
#include <cuda_bf16.h>
#include <stdint.h>

// ---------------- problem constants ----------------
#define NB   32
#define CIN  256
#define COUT 256
#define H    56
#define W    56
#define HW   (H*W)          // 3136
#define NHW  (NB*HW)        // 100352
#define CW   8              // 256 bits = 8 u32 words
#define TAPS 9

// persistent conv grid: 2 CTAs per SM on GB300 (152 SMs)
#define NSM      152
#define CONV_CTAS (2*NSM)   // 304
// item = (n, h, half-row of 28 px): 32*56*2 = 3584 items, 112 per batch
#define WHALF 28
#define IPB   (H*2)         // 112 items per batch
#define NITEMS (NB*IPB)     // 3584

// ---------------- device scratch ----------------
__device__ uint32_t g_xb[(size_t)NB*HW*CW];   // packed activations [n][h][w][8] (3.2 MB)
__device__ uint32_t g_wb[COUT*TAPS*CW];       // packed weights [oc][tap][8] (72 KB)
__device__ short    g_y[(size_t)NHW*COUT];    // conv result NHWC int16 (51 MB)
__device__ int                g_sum[COUT];
__device__ unsigned long long g_sq[COUT];
__device__ float    g_scale[COUT];
__device__ float    g_shift[COUT];
__device__ int      g_one;                    // runtime 1: pins accumulates to IMAD (fma pipe)

// ---------------- kernel 1: pack activations into bitplanes ----------------
__global__ void pack_x_kernel(const float* __restrict__ x) {
    int tid = blockIdx.x * blockDim.x + threadIdx.x;   // one thread per (n,h,w)
    if (tid >= NHW) return;
    int n   = tid / HW;
    int rem = tid - n * HW;

    uint32_t wds[CW];
#pragma unroll
    for (int i = 0; i < CW; i++) wds[i] = 0u;

#pragma unroll 8
    for (int c = 0; c < CIN; c++) {
        float v = x[(size_t)(n * CIN + c) * HW + rem];
        uint32_t bit = (v > 0.0f) ? 1u : 0u;
        wds[c >> 5] |= bit << (c & 31);
    }
    uint4* dst = reinterpret_cast<uint4*>(&g_xb[(size_t)tid * CW]);
    dst[0] = make_uint4(wds[0], wds[1], wds[2], wds[3]);
    dst[1] = make_uint4(wds[4], wds[5], wds[6], wds[7]);
}

// ---------------- kernel 2: pack weights + zero the stat accumulators ----------------
__global__ void pack_w_kernel(const float* __restrict__ w) {
    int tid = blockIdx.x * blockDim.x + threadIdx.x;   // one thread per (oc,tap,word)
    if (tid == 0) g_one = 1;
    if (tid < COUT) { g_sum[tid] = 0; g_sq[tid] = 0ull; }
    if (tid >= COUT * TAPS * CW) return;
    int oc   = tid / (TAPS * CW);
    int r    = tid - oc * (TAPS * CW);
    int tap  = r >> 3;
    int word = r & 7;

    uint32_t bits = 0u;
#pragma unroll
    for (int j = 0; j < 32; j++) {
        int ci = (word << 5) + j;
        float v = w[(size_t)(oc * CIN + ci) * TAPS + tap];
        bits |= (v > 0.f ? 1u : 0u) << j;
    }
    g_wb[tid] = bits;
}

// ---------------- kernel 3: persistent XNOR-popcount conv (CSA + IMAD offload) ----------------
__global__ void __launch_bounds__(256, 2)
conv_kernel() {
    __shared__ uint32_t sx[3][WHALF + 2][CW];          // 2.9 KB per CTA

    const int oc   = threadIdx.x;
    const int kone = g_one;                            // runtime 1 (opaque to ptxas)

    // per-thread weights (72 regs) + per-tap zero-halo correction Ct
    uint32_t wr[TAPS][CW];
    int      Ct[TAPS];
    {
        const uint32_t* wp = &g_wb[(size_t)oc * TAPS * CW];
#pragma unroll
        for (int t = 0; t < TAPS; t++) {
            int p = 0;
#pragma unroll
            for (int k = 0; k < CW; k++) {
                uint32_t v = __ldg(wp + t * CW + k);
                wr[t][k] = v;
                p += __popc(v);
            }
            Ct[t] = CIN - 2 * p;                       // contribution of a zero-halo tap
        }
    }

    int       lsum = 0;
    long long lsq  = 0;

    for (int item = blockIdx.x; item < NITEMS; item += CONV_CTAS) {
        const int n   = item / IPB;                    // 112 items per batch
        const int r2  = item - n * IPB;                // h*2 + whalf
        const int h   = r2 >> 1;
        const int wh0 = (r2 & 1) * WHALF;

        __syncthreads();                               // protect prior sx reads

        // cooperative load of x bit-tile: rows h-1..h+1, cols wh0-1..wh0+28
        const int TOT = 3 * (WHALF + 2) * CW;          // 720 words
        for (int i = oc; i < TOT; i += 256) {
            int wrd  = i & 7;
            int rest = i >> 3;
            int lc   = rest % (WHALF + 2);
            int r    = rest / (WHALF + 2);
            int gh   = h - 1 + r;
            int gw   = wh0 - 1 + lc;
            uint32_t v = 0u;
            if (gh >= 0 && gh < H && gw >= 0 && gw < W)
                v = g_xb[(((size_t)n * H + gh) * W + gw) * CW + wrd];
            sx[r][lc][wrd] = v;
        }
        __syncthreads();

        // per-item uniform h-border correction (subtracted from every pixel)
        const int invH = (h == 0 ? 0x007 : 0) | (h == H - 1 ? 0x1C0 : 0);
        int cH = 0;
        if (invH) {
#pragma unroll
            for (int t = 0; t < TAPS; t++)
                if ((invH >> t) & 1) cH += Ct[t];
        }

        short* yrow = &g_y[(((size_t)n * H + h) * W + wh0) * COUT + oc];

        for (int ol = 0; ol < WHALF; ol++) {
            int s1 = 0, s2 = 0;                        // plain / carry(x2) popcounts
#pragma unroll
            for (int g = 0; g < 3; g++) {              // tap rows: taps 3g..3g+2
                const uint4 xa0 = *reinterpret_cast<const uint4*>(&sx[g][ol + 0][0]);
                const uint4 xb0 = *reinterpret_cast<const uint4*>(&sx[g][ol + 0][4]);
                const uint4 xa1 = *reinterpret_cast<const uint4*>(&sx[g][ol + 1][0]);
                const uint4 xb1 = *reinterpret_cast<const uint4*>(&sx[g][ol + 1][4]);
                const uint4 xa2 = *reinterpret_cast<const uint4*>(&sx[g][ol + 2][0]);
                const uint4 xb2 = *reinterpret_cast<const uint4*>(&sx[g][ol + 2][4]);
                uint32_t x0[8] = {xa0.x, xa0.y, xa0.z, xa0.w, xb0.x, xb0.y, xb0.z, xb0.w};
                uint32_t x1[8] = {xa1.x, xa1.y, xa1.z, xa1.w, xb1.x, xb1.y, xb1.z, xb1.w};
                uint32_t x2[8] = {xa2.x, xa2.y, xa2.z, xa2.w, xb2.x, xb2.y, xb2.z, xb2.w};
#pragma unroll
                for (int k = 0; k < CW; k++) {
                    uint32_t a = x0[k] ^ wr[3 * g + 0][k];
                    uint32_t b = x1[k] ^ wr[3 * g + 1][k];
                    uint32_t c = x2[k] ^ wr[3 * g + 2][k];
                    uint32_t sum = a ^ b ^ c;                        // LOP3 0x96
                    uint32_t maj = (a & b) | (a & c) | (b & c);     // LOP3 0xE8
                    int p1, p2;
                    asm("popc.b32 %0, %1;" : "=r"(p1) : "r"(sum));
                    asm("popc.b32 %0, %1;" : "=r"(p2) : "r"(maj));
                    // accumulate via IMAD (fma pipe): mad with runtime 1
                    asm("mad.lo.s32 %0, %1, %2, %0;" : "+r"(s1) : "r"(p1), "r"(kone));
                    asm("mad.lo.s32 %0, %1, %2, %0;" : "+r"(s2) : "r"(p2), "r"(kone));
                }
            }
            int s  = s1 + 2 * s2;                      // exact Σ popc over 72 words
            int yv = CIN * TAPS - 2 * s - cH;          // h-border corrected (uniform)

            // rare w-border pixels: fully recompute correction (warp-uniform branch)
            if ((wh0 == 0 && ol == 0) || (wh0 == WHALF && ol == WHALF - 1)) {
                int inv = invH | (ol == 0 ? 0x049 : 0x124);
                yv = CIN * TAPS - 2 * s;
#pragma unroll
                for (int t = 0; t < TAPS; t++)
                    if ((inv >> t) & 1) yv -= Ct[t];
            }

            yrow[(size_t)ol * COUT] = (short)yv;       // NHWC: coalesced over oc
            lsum += yv;
            lsq  += (long long)(yv * yv);
        }
    }

    atomicAdd(&g_sum[oc], lsum);
    atomicAdd(&g_sq[oc], (unsigned long long)lsq);
}

// ---------------- kernel 4: BN scale/shift from exact integer stats ----------------
__global__ void stats_kernel(const float* __restrict__ gamma,
                             const float* __restrict__ beta) {
    int c = threadIdx.x;
    const double cnt = (double)NHW;
    double mean = (double)g_sum[c] / cnt;
    double ex2  = (double)(long long)g_sq[c] / cnt;
    double var  = ex2 - mean * mean;
    double inv  = 1.0 / sqrt(var + 1e-5);
    double sc   = (double)gamma[c] * inv;
    g_scale[c] = (float)sc;
    g_shift[c] = (float)((double)beta[c] - mean * sc);
}

// ---------------- kernel 5: BN apply + NHWC -> NCHW ----------------
#define WT 28
__global__ void __launch_bounds__(256)
apply_kernel(float* __restrict__ out) {
    __shared__ float sy[WT * 257];                     // padded: conflict-free both phases
    const int wt = blockIdx.x, h = blockIdx.y, n = blockIdx.z;
    const int tid = threadIdx.x;

    for (int idx = tid; idx < WT * COUT; idx += 256) {
        int lw = idx >> 8;
        int oc = idx & 255;
        int gw = wt * WT + lw;
        float yv = (float)g_y[(((size_t)n * H + h) * W + gw) * COUT + oc];
        sy[lw * 257 + oc] = yv * g_scale[oc] + g_shift[oc];
    }
    __syncthreads();
    for (int idx = tid; idx < WT * COUT; idx += 256) {
        int oc = idx / WT;
        int lw = idx - oc * WT;
        out[(((size_t)n * COUT + oc) * H + h) * W + wt * WT + lw] = sy[lw * 257 + oc];
    }
}

// ---------------- launch ----------------
extern "C" void kernel_launch(void* const* d_in, const int* in_sizes, int n_in,
                              void* d_out, int out_size) {
    const float* x     = (const float*)d_in[0];
    const float* w     = (const float*)d_in[1];
    const float* gamma = (const float*)d_in[2];
    const float* beta  = (const float*)d_in[3];
    float* out = (float*)d_out;

    pack_x_kernel<<<(NHW + 255) / 256, 256>>>(x);
    pack_w_kernel<<<(COUT * TAPS * CW + 255) / 256, 256>>>(w);
    conv_kernel<<<CONV_CTAS, 256>>>();
    stats_kernel<<<1, COUT>>>(gamma, beta);
    apply_kernel<<<dim3(W / WT, H, NB), 256>>>(out);
}

// round 16
// speedup vs baseline: 1.0264x; 1.0264x over previous
#include <cuda_runtime.h>
#include <cuda_bf16.h>
#include <stdint.h>

// ---------------- problem constants ----------------
#define NB   32
#define CIN  256
#define COUT 256
#define H    56
#define W    56
#define HW   (H*W)          // 3136
#define NHW  (NB*HW)        // 100352
#define CW   8              // 256 bits = 8 u32 words
#define TAPS 9

// persistent conv grid: 2 CTAs per SM on GB300 (152 SMs)
#define NSM      152
#define CONV_CTAS (2*NSM)   // 304
// item = (n, h, half-row of 28 px): 32*56*2 = 3584 items, 112 per batch
#define WHALF 28
#define IPB   (H*2)         // 112 items per batch
#define NITEMS (NB*IPB)     // 3584

// combined pack kernel grid split
#define XBLK ((NHW + 255)/256)              // 392 blocks: pack_x
#define WBLK ((COUT*TAPS*CW + 255)/256)     // 72 blocks: pack_w + zero stats

// ---------------- device scratch ----------------
__device__ uint32_t g_xb[(size_t)NB*HW*CW];   // packed activations [n][h][w][8] (3.2 MB)
__device__ uint32_t g_wb[COUT*TAPS*CW];       // packed weights [oc][tap][8] (72 KB)
__device__ short    g_y[(size_t)NHW*COUT];    // conv result NHWC int16 (51 MB)
__device__ int                g_sum[COUT];
__device__ unsigned long long g_sq[COUT];
__device__ float    g_scale[COUT];            // holds inv_std after conv
__device__ float    g_shift[COUT];            // holds mean after conv
__device__ int      g_done;                   // conv CTA completion counter

// ---------------- kernel 1: combined pack (x bitplanes | w bitplanes + zero stats) ----------------
__global__ void pack_kernel(const float* __restrict__ x, const float* __restrict__ w) {
    if (blockIdx.x < XBLK) {
        // ---- pack x ----
        int tid = blockIdx.x * 256 + threadIdx.x;      // one thread per (n,h,w)
        if (tid >= NHW) return;
        int n   = tid / HW;
        int rem = tid - n * HW;

        uint32_t wds[CW];
#pragma unroll
        for (int i = 0; i < CW; i++) wds[i] = 0u;

#pragma unroll 8
        for (int c = 0; c < CIN; c++) {
            float v = x[(size_t)(n * CIN + c) * HW + rem];
            uint32_t bit = (v > 0.0f) ? 1u : 0u;
            wds[c >> 5] |= bit << (c & 31);
        }
        uint4* dst = reinterpret_cast<uint4*>(&g_xb[(size_t)tid * CW]);
        dst[0] = make_uint4(wds[0], wds[1], wds[2], wds[3]);
        dst[1] = make_uint4(wds[4], wds[5], wds[6], wds[7]);
    } else {
        // ---- pack w + zero accumulators ----
        int tid = (blockIdx.x - XBLK) * 256 + threadIdx.x;
        if (tid == 0) g_done = 0;
        if (tid < COUT) { g_sum[tid] = 0; g_sq[tid] = 0ull; }
        if (tid >= COUT * TAPS * CW) return;
        int oc   = tid / (TAPS * CW);
        int r    = tid - oc * (TAPS * CW);
        int tap  = r >> 3;
        int word = r & 7;

        uint32_t bits = 0u;
#pragma unroll
        for (int j = 0; j < 32; j++) {
            int ci = (word << 5) + j;
            float v = w[(size_t)(oc * CIN + ci) * TAPS + tap];
            bits |= (v > 0.f ? 1u : 0u) << j;
        }
        g_wb[tid] = bits;
    }
}

// ---------------- kernel 2: persistent XNOR-popcount conv + fused BN stats ----------------
__global__ void __launch_bounds__(256, 2)
conv_kernel() {
    __shared__ uint32_t sx[3][WHALF + 2][CW];          // 2.9 KB per CTA
    __shared__ int islast;

    const int oc = threadIdx.x;

    // per-thread weights (72 regs) + per-tap zero-halo correction Ct
    uint32_t wr[TAPS][CW];
    int      Ct[TAPS];
    {
        const uint32_t* wp = &g_wb[(size_t)oc * TAPS * CW];
#pragma unroll
        for (int t = 0; t < TAPS; t++) {
            int p = 0;
#pragma unroll
            for (int k = 0; k < CW; k++) {
                uint32_t v = __ldg(wp + t * CW + k);
                wr[t][k] = v;
                p += __popc(v);
            }
            Ct[t] = CIN - 2 * p;                       // contribution of a zero-halo tap
        }
    }

    int       lsum = 0;
    long long lsq  = 0;

    for (int item = blockIdx.x; item < NITEMS; item += CONV_CTAS) {
        const int n   = item / IPB;                    // 112 items per batch
        const int r2  = item - n * IPB;                // h*2 + whalf
        const int h   = r2 >> 1;
        const int wh0 = (r2 & 1) * WHALF;

        __syncthreads();                               // protect prior sx reads

        // cooperative load of x bit-tile: rows h-1..h+1, cols wh0-1..wh0+28
        const int TOT = 3 * (WHALF + 2) * CW;          // 720 words
        for (int i = oc; i < TOT; i += 256) {
            int wrd  = i & 7;
            int rest = i >> 3;
            int lc   = rest % (WHALF + 2);
            int r    = rest / (WHALF + 2);
            int gh   = h - 1 + r;
            int gw   = wh0 - 1 + lc;
            uint32_t v = 0u;
            if (gh >= 0 && gh < H && gw >= 0 && gw < W)
                v = g_xb[(((size_t)n * H + gh) * W + gw) * CW + wrd];
            sx[r][lc][wrd] = v;
        }
        __syncthreads();

        // per-item uniform h-border correction (subtracted from every pixel)
        const int invH = (h == 0 ? 0x007 : 0) | (h == H - 1 ? 0x1C0 : 0);
        int cH = 0;
        if (invH) {
#pragma unroll
            for (int t = 0; t < TAPS; t++)
                if ((invH >> t) & 1) cH += Ct[t];
        }

        short* yrow = &g_y[(((size_t)n * H + h) * W + wh0) * COUT + oc];
        int isum = 0;                                  // per-item int32 stats
        int isq  = 0;                                  // max 28*2304^2 = 1.49e8 < 2^31

        for (int ol = 0; ol < WHALF; ol++) {
            int s1 = 0, s2 = 0;                        // plain / carry(x2) popcounts
#pragma unroll
            for (int g = 0; g < 3; g++) {              // tap rows: taps 3g..3g+2
                const uint4 xa0 = *reinterpret_cast<const uint4*>(&sx[g][ol + 0][0]);
                const uint4 xb0 = *reinterpret_cast<const uint4*>(&sx[g][ol + 0][4]);
                const uint4 xa1 = *reinterpret_cast<const uint4*>(&sx[g][ol + 1][0]);
                const uint4 xb1 = *reinterpret_cast<const uint4*>(&sx[g][ol + 1][4]);
                const uint4 xa2 = *reinterpret_cast<const uint4*>(&sx[g][ol + 2][0]);
                const uint4 xb2 = *reinterpret_cast<const uint4*>(&sx[g][ol + 2][4]);
                uint32_t x0[8] = {xa0.x, xa0.y, xa0.z, xa0.w, xb0.x, xb0.y, xb0.z, xb0.w};
                uint32_t x1[8] = {xa1.x, xa1.y, xa1.z, xa1.w, xb1.x, xb1.y, xb1.z, xb1.w};
                uint32_t x2[8] = {xa2.x, xa2.y, xa2.z, xa2.w, xb2.x, xb2.y, xb2.z, xb2.w};
#pragma unroll
                for (int k = 0; k < CW; k++) {
                    uint32_t a = x0[k] ^ wr[3 * g + 0][k];
                    uint32_t b = x1[k] ^ wr[3 * g + 1][k];
                    uint32_t c = x2[k] ^ wr[3 * g + 2][k];
                    uint32_t sum = a ^ b ^ c;                        // LOP3 0x96
                    uint32_t maj = (a & b) | (a & c) | (b & c);     // LOP3 0xE8
                    s1 += __popc(sum);
                    s2 += __popc(maj);
                }
            }
            int s  = s1 + 2 * s2;                      // exact Σ popc over 72 words
            int yv = CIN * TAPS - 2 * s - cH;          // h-border corrected (uniform)

            // rare w-border pixels: fully recompute correction (warp-uniform branch)
            if ((wh0 == 0 && ol == 0) || (wh0 == WHALF && ol == WHALF - 1)) {
                int inv = invH | (ol == 0 ? 0x049 : 0x124);
                yv = CIN * TAPS - 2 * s;
#pragma unroll
                for (int t = 0; t < TAPS; t++)
                    if ((inv >> t) & 1) yv -= Ct[t];
            }

            yrow[(size_t)ol * COUT] = (short)yv;       // NHWC: coalesced over oc
            isum += yv;
            isq  += yv * yv;
        }
        lsum += isum;
        lsq  += (long long)isq;
    }

    atomicAdd(&g_sum[oc], lsum);
    atomicAdd(&g_sq[oc], (unsigned long long)lsq);
    __threadfence();

    // ---- last CTA computes inv_std/mean (fused stats) ----
    if (threadIdx.x == 0)
        islast = (atomicAdd(&g_done, 1) == CONV_CTAS - 1);
    __syncthreads();
    if (islast) {
        int c = oc;
        int                s = atomicAdd(&g_sum[c], 0);             // L2-coherent read
        unsigned long long q = atomicAdd(&g_sq[c], 0ull);
        const double cnt  = (double)NHW;
        double mean = (double)s / cnt;
        double ex2  = (double)(long long)q / cnt;
        double var  = ex2 - mean * mean;
        double inv  = 1.0 / sqrt(var + 1e-5);
        g_scale[c] = (float)inv;                                    // inv_std
        g_shift[c] = (float)mean;                                   // mean
    }
}

// ---------------- kernel 3: BN apply (folds gamma/beta) + NHWC -> NCHW ----------------
#define WT 28
__global__ void __launch_bounds__(256)
apply_kernel(float* __restrict__ out,
             const float* __restrict__ gamma,
             const float* __restrict__ beta) {
    __shared__ float sy[WT * 257];                     // padded: conflict-free both phases
    __shared__ float ssc[COUT], ssh[COUT];
    const int wt = blockIdx.x, h = blockIdx.y, n = blockIdx.z;
    const int tid = threadIdx.x;

    {   // fold gamma/beta with (inv_std, mean) once per CTA
        float inv  = g_scale[tid];
        float mean = g_shift[tid];
        float sc   = gamma[tid] * inv;
        ssc[tid] = sc;
        ssh[tid] = beta[tid] - mean * sc;
    }
    __syncthreads();

    for (int idx = tid; idx < WT * COUT; idx += 256) {
        int lw = idx >> 8;
        int oc = idx & 255;
        int gw = wt * WT + lw;
        float yv = (float)g_y[(((size_t)n * H + h) * W + gw) * COUT + oc];
        sy[lw * 257 + oc] = yv * ssc[oc] + ssh[oc];
    }
    __syncthreads();
    for (int idx = tid; idx < WT * COUT; idx += 256) {
        int oc = idx / WT;
        int lw = idx - oc * WT;
        out[(((size_t)n * COUT + oc) * H + h) * W + wt * WT + lw] = sy[lw * 257 + oc];
    }
}

// ---------------- launch ----------------
extern "C" void kernel_launch(void* const* d_in, const int* in_sizes, int n_in,
                              void* d_out, int out_size) {
    const float* x     = (const float*)d_in[0];
    const float* w     = (const float*)d_in[1];
    const float* gamma = (const float*)d_in[2];
    const float* beta  = (const float*)d_in[3];
    float* out = (float*)d_out;

    pack_kernel<<<XBLK + WBLK, 256>>>(x, w);
    conv_kernel<<<CONV_CTAS, 256>>>();
    apply_kernel<<<dim3(W / WT, H, NB), 256>>>(out, gamma, beta);
}